// round 4
// baseline (speedup 1.0000x reference)
#include <cuda_runtime.h>
#include <cuda_fp16.h>

// ============================================================================
// Sinkhorn, N=8, P=2048, EPS=0.1, 50 iters.
//   a = (mu+1e-8)/(K b),  b = (nu+1e-8)/(K^T a),  b0 = 1,  K = exp(-C/eps)
// K stored fp16 (67MB, L2-resident). Per iteration:
//   k_red : b_j = (nu_j+1e-8) / sum_k partials[k][j]       (tiny, 8MB L2)
//   k_iter: per 16-row band: pass1 row-GEMV (K from L2 -> also stashed in
//           SMEM), pass2 column partials for b (K re-read from SMEM, not L2).
// K traverses L2 ONCE per iteration. Deterministic (no float atomics).
//
// Output (fp32): [ cost(8) | pi(8*2048*2048) | C(8*2048*2048) ],
// pi recomputed from ORIGINAL fp32 C: pi = exp(ln a_i + ln b_j - 10*C_ij).
// ============================================================================

#define N_B   8
#define P     2048
#define NITER 50
#define BLKS  128          // bands per batch
#define RB    (P / BLKS)   // 16 rows per band
#define TPB   256
#define INV_EPS 10.0f

// scratch (static __device__ arrays: the sanctioned scratch mechanism)
static __device__ __half2 K2[(size_t)N_B * P * (P / 2)];  // 67 MB fp16 kernel
static __device__ float   partials[(size_t)N_B * BLKS * P]; // 8 MB col partials
static __device__ float   b_buf[N_B * P];
static __device__ float   a_buf[N_B * P];
static __device__ float   lb_buf[N_B * P];                // ln b (final)
static __device__ float   cost_part[N_B * 128];

// ---------------------------------------------------------------------------
// K = exp(-C/eps), fp32 -> fp16
__global__ __launch_bounds__(256) void k_prep(const float* __restrict__ C) {
    size_t i = (size_t)blockIdx.x * 256 + threadIdx.x;  // float4 idx, 8388608
    float4 c = __ldcs(reinterpret_cast<const float4*>(C) + i);
    K2[2 * i]     = __floats2half2_rn(__expf(-INV_EPS * c.x), __expf(-INV_EPS * c.y));
    K2[2 * i + 1] = __floats2half2_rn(__expf(-INV_EPS * c.z), __expf(-INV_EPS * c.w));
}

// ---------------------------------------------------------------------------
// b reduction. grid (8 col-groups, N_B), 256 threads. it==0 -> b = 1.
__global__ __launch_bounds__(256) void k_red(const float* __restrict__ nu, int it) {
    int n = blockIdx.y;
    int j = blockIdx.x * 256 + threadIdx.x;
    if (it == 0) { b_buf[n * P + j] = 1.0f; return; }
    const float* pp = partials + (size_t)n * BLKS * P + j;
    float s = 0.0f;
#pragma unroll 8
    for (int k = 0; k < BLKS; k++) s += pp[(size_t)k * P];
    b_buf[n * P + j] = __fdividef(nu[n * P + j] + 1e-8f, s);
}

// ---------------------------------------------------------------------------
// One Sinkhorn iteration over one 16-row band. grid (BLKS, N_B), 256 thr.
// dynamic smem: Ksh[RB*1024] half2 (64KB) | bsh[P] float (8KB) | ash[RB]
extern __shared__ char smem_raw[];
__global__ __launch_bounds__(TPB, 2) void k_iter(const float* __restrict__ mu) {
    int n   = blockIdx.y;
    int blk = blockIdx.x;
    int tid = threadIdx.x;

    __half2* Ksh = reinterpret_cast<__half2*>(smem_raw);             // RB*1024
    float*   bsh = reinterpret_cast<float*>(smem_raw + RB * 1024 * 4);  // P
    float*   ash = bsh + P;                                          // RB

    // load b
    for (int j = tid; j < P; j += TPB) bsh[j] = b_buf[n * P + j];
    __syncthreads();

    // pass 1: row GEMV, 16 row-groups x 16 lanes; stash band into SMEM.
    int g = tid >> 4;   // row in band
    int l = tid & 15;
    int row = blk * RB + g;
    const __half2* Kr = K2 + (size_t)(n * P + row) * (P / 2);
    float acc = 0.0f;
#pragma unroll
    for (int k = 0; k < 16; k++) {
        int p0 = (k * 16 + l) * 4;   // half2 index, 16B per lane
        uint4 kk = *reinterpret_cast<const uint4*>(Kr + p0);
        *reinterpret_cast<uint4*>(Ksh + g * 1024 + p0) = kk;
        float4 e0 = *reinterpret_cast<const float4*>(bsh + 2 * p0);
        float4 e1 = *reinterpret_cast<const float4*>(bsh + 2 * p0 + 4);
        float2 f;
        f = __half22float2(*reinterpret_cast<__half2*>(&kk.x));
        acc += f.x * e0.x + f.y * e0.y;
        f = __half22float2(*reinterpret_cast<__half2*>(&kk.y));
        acc += f.x * e0.z + f.y * e0.w;
        f = __half22float2(*reinterpret_cast<__half2*>(&kk.z));
        acc += f.x * e1.x + f.y * e1.y;
        f = __half22float2(*reinterpret_cast<__half2*>(&kk.w));
        acc += f.x * e1.z + f.y * e1.w;
    }
#pragma unroll
    for (int o = 8; o; o >>= 1)
        acc += __shfl_down_sync(0xffffffffu, acc, o, 16);
    if (l == 0) {
        float av = __fdividef(mu[n * P + row] + 1e-8f, acc);
        ash[g] = av;
        a_buf[n * P + row] = av;
    }
    __syncthreads();

    // pass 2: column partials from SMEM band. Thread owns 8 columns.
    float a0 = 0.f, a1 = 0.f, a2 = 0.f, a3 = 0.f;
    float a4 = 0.f, a5 = 0.f, a6 = 0.f, a7 = 0.f;
    const __half2* Kp = Ksh + tid * 4;
#pragma unroll
    for (int i = 0; i < RB; i++) {
        float ai = ash[i];
        uint4 kk = *reinterpret_cast<const uint4*>(Kp + (size_t)i * 1024);
        float2 f0 = __half22float2(*reinterpret_cast<__half2*>(&kk.x));
        float2 f1 = __half22float2(*reinterpret_cast<__half2*>(&kk.y));
        float2 f2 = __half22float2(*reinterpret_cast<__half2*>(&kk.z));
        float2 f3 = __half22float2(*reinterpret_cast<__half2*>(&kk.w));
        a0 += ai * f0.x;  a1 += ai * f0.y;
        a2 += ai * f1.x;  a3 += ai * f1.y;
        a4 += ai * f2.x;  a5 += ai * f2.y;
        a6 += ai * f3.x;  a7 += ai * f3.y;
    }
    float* wp = partials + (size_t)(n * BLKS + blk) * P + tid * 8;
    *reinterpret_cast<float4*>(wp)     = make_float4(a0, a1, a2, a3);
    *reinterpret_cast<float4*>(wp + 4) = make_float4(a4, a5, a6, a7);
}

// ---------------------------------------------------------------------------
// final ln b. grid (N_B), 256 threads.
__global__ __launch_bounds__(256) void k_bfin(const float* __restrict__ nu) {
    int n = blockIdx.x;
    const float* pp = partials + (size_t)n * BLKS * P;
    for (int j = threadIdx.x; j < P; j += 256) {
        float s = 0.0f;
#pragma unroll 8
        for (int k = 0; k < BLKS; k++) s += pp[(size_t)k * P + j];
        lb_buf[n * P + j] = __logf(nu[n * P + j] + 1e-8f) - __logf(s);
    }
}

// ---------------------------------------------------------------------------
// pi = exp(ln a + ln b - 10*C) from ORIGINAL fp32 C; cost partials; C copy
__global__ __launch_bounds__(256) void k_epi(const float* __restrict__ C,
                                             float* __restrict__ pi_out,
                                             float* __restrict__ c_out) {
    int n    = blockIdx.y;
    int row0 = blockIdx.x * 16;
    __shared__ float lbsh[P];
    __shared__ float sred[256];
    for (int j = threadIdx.x; j < P; j += 256) lbsh[j] = lb_buf[n * P + j];
    __syncthreads();
    float local = 0.0f;
    for (int r = 0; r < 16; r++) {
        int row = row0 + r;
        float la = __logf(a_buf[n * P + row]);
        size_t base = ((size_t)n * P + row) * P;
        const float4* Cr = reinterpret_cast<const float4*>(C + base);
        float4* Pr = pi_out ? reinterpret_cast<float4*>(pi_out + base) : nullptr;
        float4* Or = c_out  ? reinterpret_cast<float4*>(c_out  + base) : nullptr;
        for (int q = threadIdx.x; q < P / 4; q += 256) {
            float4 c = __ldcs(Cr + q);
            int j = q * 4;
            float4 pi;
            pi.x = __expf(la + lbsh[j]     - INV_EPS * c.x);
            pi.y = __expf(la + lbsh[j + 1] - INV_EPS * c.y);
            pi.z = __expf(la + lbsh[j + 2] - INV_EPS * c.z);
            pi.w = __expf(la + lbsh[j + 3] - INV_EPS * c.w);
            if (Pr) __stcs(Pr + q, pi);
            if (Or) __stcs(Or + q, c);
            local += pi.x * c.x + pi.y * c.y + pi.z * c.z + pi.w * c.w;
        }
    }
    sred[threadIdx.x] = local;
    __syncthreads();
    for (int o = 128; o; o >>= 1) {
        if (threadIdx.x < o) sred[threadIdx.x] += sred[threadIdx.x + o];
        __syncthreads();
    }
    if (threadIdx.x == 0) cost_part[n * 128 + blockIdx.x] = sred[0];
}

__global__ __launch_bounds__(128) void k_cost(float* __restrict__ out) {
    int n = blockIdx.x;
    __shared__ float s[128];
    s[threadIdx.x] = cost_part[n * 128 + threadIdx.x];
    __syncthreads();
    for (int o = 64; o; o >>= 1) {
        if (threadIdx.x < o) s[threadIdx.x] += s[threadIdx.x + o];
        __syncthreads();
    }
    if (threadIdx.x == 0) out[n] = s[0];
}

// ---------------------------------------------------------------------------
extern "C" void kernel_launch(void* const* d_in, const int* in_sizes, int n_in,
                              void* d_out, int out_size) {
    const float* C  = (const float*)d_in[0];
    const float* mu = (const float*)d_in[1];
    const float* nu = (const float*)d_in[2];
    float* out = (float*)d_out;

    const long long PI_ELEMS = (long long)N_B * P * P;  // 33554432
    float* pi_out = nullptr;
    float* c_out  = nullptr;
    if ((long long)out_size >= 8 + PI_ELEMS)     pi_out = out + 8;
    if ((long long)out_size >= 8 + 2 * PI_ELEMS) c_out  = out + 8 + PI_ELEMS;

    const int ITER_SMEM = RB * 1024 * 4 + P * 4 + RB * 4 + 16;  // ~72.3 KB
    cudaFuncSetAttribute(k_iter, cudaFuncAttributeMaxDynamicSharedMemorySize,
                         ITER_SMEM);

    k_prep<<<32768, 256>>>(C);
    for (int it = 0; it < NITER; it++) {
        k_red<<<dim3(8, N_B), 256>>>(nu, it);
        k_iter<<<dim3(BLKS, N_B), TPB, ITER_SMEM>>>(mu);
    }
    k_bfin<<<N_B, 256>>>(nu);
    k_epi<<<dim3(128, N_B), 256>>>(C, pi_out, c_out);
    k_cost<<<N_B, 128>>>(out);
}

// round 5
// speedup vs baseline: 1.4337x; 1.4337x over previous
#include <cuda_runtime.h>
#include <cuda_fp16.h>

// ============================================================================
// Sinkhorn, N=8, P=2048, EPS=0.1, 50 iters.
//   a = (mu+1e-8)/(K b),  b = (nu+1e-8)/(K^T a),  b0 = 1,  K = exp(-C/eps)
// K fp16 (67MB, L2-resident). ONE persistent kernel runs all 50 iterations
// with a software grid barrier (all blocks co-resident via occupancy calc).
// Per iteration: band pass (row GEMV for a + smem-staged band reused for
// register-resident column partials -> K traverses L2 once), grid sync,
// distributed b-reduce, grid sync. Deterministic (fixed reduction order,
// no float atomics).
//
// Output (fp32): [ cost(8) | pi(8*2048*2048) | C(8*2048*2048) ],
// pi recomputed from ORIGINAL fp32 C: pi = exp(ln a_i + ln b_j - 10*C_ij).
// ============================================================================

#define N_B   8
#define P     2048
#define NITER 50
#define NBANDS 128         // 16-row bands per batch
#define RB    16           // rows per band
#define TPB   256
#define MAXBB 64           // max blocks per batch (partials array bound)
#define INV_EPS 10.0f

// scratch (static __device__ arrays: the sanctioned scratch mechanism)
static __device__ __half2 K2[(size_t)N_B * P * (P / 2)];    // 67 MB fp16 kernel
static __device__ float   partials[(size_t)N_B * MAXBB * P]; // 4 MB col partials
static __device__ float   b_buf[N_B * P];
static __device__ float   a_buf[N_B * P];
static __device__ float   cost_part[N_B * 128];

// software grid barrier state (zero-initialized; ctr returns to 0 each sync)
static __device__ unsigned bar_ctr;
static __device__ volatile unsigned bar_gen;

__device__ __forceinline__ void grid_sync(int G) {
    __syncthreads();
    if (threadIdx.x == 0) {
        __threadfence();
        unsigned gen = bar_gen;
        if (atomicAdd(&bar_ctr, 1u) == (unsigned)(G - 1)) {
            bar_ctr = 0;
            __threadfence();
            bar_gen = gen + 1;
        } else {
            while (bar_gen == gen) { }
            __threadfence();
        }
    }
    __syncthreads();
}

// ---------------------------------------------------------------------------
// K = exp(-C/eps), fp32 -> fp16
__global__ __launch_bounds__(256) void k_prep(const float* __restrict__ C) {
    size_t i = (size_t)blockIdx.x * 256 + threadIdx.x;  // float4 idx, 8388608
    float4 c = __ldcs(reinterpret_cast<const float4*>(C) + i);
    K2[2 * i]     = __floats2half2_rn(__expf(-INV_EPS * c.x), __expf(-INV_EPS * c.y));
    K2[2 * i + 1] = __floats2half2_rn(__expf(-INV_EPS * c.z), __expf(-INV_EPS * c.w));
}

// ---------------------------------------------------------------------------
// Persistent iteration kernel. grid = G = 8*Bb blocks, TPB threads.
// dynamic smem: Ksh[RB*1024] half2 (64KB) | bsh[P] float (8KB) | ash[RB]
extern __shared__ char smem_raw[];
__global__ __launch_bounds__(TPB, 2) void k_main(const float* __restrict__ mu,
                                                 const float* __restrict__ nu,
                                                 int G, int Bb) {
    __half2* Ksh = reinterpret_cast<__half2*>(smem_raw);               // RB*1024
    float*   bsh = reinterpret_cast<float*>(smem_raw + RB * 1024 * 4); // P
    float*   ash = bsh + P;                                            // RB

    int tid = threadIdx.x;
    int n   = blockIdx.x / Bb;     // batch
    int r   = blockIdx.x % Bb;     // block index within batch
    int w   = tid >> 5;            // warp 0..7
    int l   = tid & 31;

    // b0 = 1
    for (int e = blockIdx.x * TPB + tid; e < N_B * P; e += G * TPB)
        b_buf[e] = 1.0f;
    grid_sync(G);

    for (int it = 0; it < NITER; it++) {
        // load b for my batch (written by other blocks -> bypass L1)
        for (int j4 = tid; j4 < P / 4; j4 += TPB) {
            float4 bv = __ldcg(reinterpret_cast<const float4*>(b_buf + n * P) + j4);
            *reinterpret_cast<float4*>(bsh + j4 * 4) = bv;
        }
        __syncthreads();

        // column-partial accumulators (8 columns per thread), across all bands
        float a0 = 0.f, a1 = 0.f, a2 = 0.f, a3 = 0.f;
        float a4 = 0.f, a5 = 0.f, a6 = 0.f, a7 = 0.f;

        for (int band = r; band < NBANDS; band += Bb) {
            // pass 1: row GEMV, one warp per row (2 sweeps of 8 rows),
            // staging the band into SMEM with contiguous warp stores.
#pragma unroll
            for (int h = 0; h < 2; h++) {
                int rloc = h * 8 + w;
                int row  = band * RB + rloc;
                const __half2* Kr = K2 + (size_t)(n * P + row) * (P / 2);
                float acc = 0.0f;
#pragma unroll
                for (int k = 0; k < 8; k++) {
                    int p0 = (k * 32 + l) * 4;   // half2 idx, 16B per lane
                    uint4 kk = *reinterpret_cast<const uint4*>(Kr + p0);
                    *reinterpret_cast<uint4*>(Ksh + rloc * 1024 + p0) = kk;
                    float4 e0 = *reinterpret_cast<const float4*>(bsh + 2 * p0);
                    float4 e1 = *reinterpret_cast<const float4*>(bsh + 2 * p0 + 4);
                    float2 f;
                    f = __half22float2(*reinterpret_cast<__half2*>(&kk.x));
                    acc += f.x * e0.x + f.y * e0.y;
                    f = __half22float2(*reinterpret_cast<__half2*>(&kk.y));
                    acc += f.x * e0.z + f.y * e0.w;
                    f = __half22float2(*reinterpret_cast<__half2*>(&kk.z));
                    acc += f.x * e1.x + f.y * e1.y;
                    f = __half22float2(*reinterpret_cast<__half2*>(&kk.w));
                    acc += f.x * e1.z + f.y * e1.w;
                }
#pragma unroll
                for (int o = 16; o; o >>= 1)
                    acc += __shfl_down_sync(0xffffffffu, acc, o);
                if (l == 0) {
                    float av = __fdividef(mu[n * P + row] + 1e-8f, acc);
                    ash[rloc] = av;
                    a_buf[n * P + row] = av;
                }
            }
            __syncthreads();

            // pass 2: column partials from the SMEM band (8 cols/thread).
#pragma unroll
            for (int i = 0; i < RB; i++) {
                float ai = ash[i];
                uint4 kk = *reinterpret_cast<const uint4*>(Ksh + i * 1024 + tid * 4);
                float2 f0 = __half22float2(*reinterpret_cast<__half2*>(&kk.x));
                float2 f1 = __half22float2(*reinterpret_cast<__half2*>(&kk.y));
                float2 f2 = __half22float2(*reinterpret_cast<__half2*>(&kk.z));
                float2 f3 = __half22float2(*reinterpret_cast<__half2*>(&kk.w));
                a0 += ai * f0.x;  a1 += ai * f0.y;
                a2 += ai * f1.x;  a3 += ai * f1.y;
                a4 += ai * f2.x;  a5 += ai * f2.y;
                a6 += ai * f3.x;  a7 += ai * f3.y;
            }
            __syncthreads();   // before next band overwrites Ksh
        }

        // publish this block's column partials
        float* wp = partials + (size_t)(n * Bb + r) * P + tid * 8;
        *reinterpret_cast<float4*>(wp)     = make_float4(a0, a1, a2, a3);
        *reinterpret_cast<float4*>(wp + 4) = make_float4(a4, a5, a6, a7);

        grid_sync(G);

        // distributed b-reduce: b_j = (nu_j+1e-8) / sum_k partials[k][j]
        for (int e = blockIdx.x * TPB + tid; e < N_B * P; e += G * TPB) {
            int nn = e >> 11, j = e & (P - 1);
            const float* pp = partials + (size_t)nn * Bb * P + j;
            float s = 0.0f;
            for (int k = 0; k < Bb; k++) s += __ldcg(pp + (size_t)k * P);
            b_buf[e] = __fdividef(nu[e] + 1e-8f, s);
        }

        grid_sync(G);
    }
}

// ---------------------------------------------------------------------------
// pi = exp(ln a + ln b - 10*C) from ORIGINAL fp32 C; cost partials; C copy
__global__ __launch_bounds__(256) void k_epi(const float* __restrict__ C,
                                             float* __restrict__ pi_out,
                                             float* __restrict__ c_out) {
    int n    = blockIdx.y;
    int row0 = blockIdx.x * 16;
    __shared__ float lbsh[P];
    __shared__ float sred[256];
    for (int j = threadIdx.x; j < P; j += 256)
        lbsh[j] = __logf(b_buf[n * P + j]);
    __syncthreads();
    float local = 0.0f;
    for (int r = 0; r < 16; r++) {
        int row = row0 + r;
        float la = __logf(a_buf[n * P + row]);
        size_t base = ((size_t)n * P + row) * P;
        const float4* Cr = reinterpret_cast<const float4*>(C + base);
        float4* Pr = pi_out ? reinterpret_cast<float4*>(pi_out + base) : nullptr;
        float4* Or = c_out  ? reinterpret_cast<float4*>(c_out  + base) : nullptr;
        for (int q = threadIdx.x; q < P / 4; q += 256) {
            float4 c = __ldcs(Cr + q);
            int j = q * 4;
            float4 pi;
            pi.x = __expf(la + lbsh[j]     - INV_EPS * c.x);
            pi.y = __expf(la + lbsh[j + 1] - INV_EPS * c.y);
            pi.z = __expf(la + lbsh[j + 2] - INV_EPS * c.z);
            pi.w = __expf(la + lbsh[j + 3] - INV_EPS * c.w);
            if (Pr) __stcs(Pr + q, pi);
            if (Or) __stcs(Or + q, c);
            local += pi.x * c.x + pi.y * c.y + pi.z * c.z + pi.w * c.w;
        }
    }
    sred[threadIdx.x] = local;
    __syncthreads();
    for (int o = 128; o; o >>= 1) {
        if (threadIdx.x < o) sred[threadIdx.x] += sred[threadIdx.x + o];
        __syncthreads();
    }
    if (threadIdx.x == 0) cost_part[n * 128 + blockIdx.x] = sred[0];
}

__global__ __launch_bounds__(128) void k_cost(float* __restrict__ out) {
    int n = blockIdx.x;
    __shared__ float s[128];
    s[threadIdx.x] = cost_part[n * 128 + threadIdx.x];
    __syncthreads();
    for (int o = 64; o; o >>= 1) {
        if (threadIdx.x < o) s[threadIdx.x] += s[threadIdx.x + o];
        __syncthreads();
    }
    if (threadIdx.x == 0) out[n] = s[0];
}

// ---------------------------------------------------------------------------
extern "C" void kernel_launch(void* const* d_in, const int* in_sizes, int n_in,
                              void* d_out, int out_size) {
    const float* C  = (const float*)d_in[0];
    const float* mu = (const float*)d_in[1];
    const float* nu = (const float*)d_in[2];
    float* out = (float*)d_out;

    const long long PI_ELEMS = (long long)N_B * P * P;  // 33554432
    float* pi_out = nullptr;
    float* c_out  = nullptr;
    if ((long long)out_size >= 8 + PI_ELEMS)     pi_out = out + 8;
    if ((long long)out_size >= 8 + 2 * PI_ELEMS) c_out  = out + 8 + PI_ELEMS;

    const int ITER_SMEM = RB * 1024 * 4 + P * 4 + RB * 4 + 32;  // ~72.3 KB
    static int G = 0, Bb = 0;
    if (G == 0) {   // pure host-side computation, deterministic per process
        cudaFuncSetAttribute(k_main, cudaFuncAttributeMaxDynamicSharedMemorySize,
                             ITER_SMEM);
        int dev = 0, nsm = 148, maxb = 1;
        cudaGetDevice(&dev);
        cudaDeviceGetAttribute(&nsm, cudaDevAttrMultiProcessorCount, dev);
        cudaOccupancyMaxActiveBlocksPerMultiprocessor(&maxb, k_main, TPB, ITER_SMEM);
        if (maxb < 1) maxb = 1;
        long long tot = (long long)nsm * maxb;
        Bb = (int)(tot / N_B);
        if (Bb > MAXBB) Bb = MAXBB;
        if (Bb < 1) Bb = 1;
        G = Bb * N_B;
    }

    k_prep<<<32768, 256>>>(C);
    k_main<<<G, TPB, ITER_SMEM>>>(mu, nu, G, Bb);
    k_epi<<<dim3(128, N_B), 256>>>(C, pi_out, c_out);
    k_cost<<<N_B, 128>>>(out);
}

// round 7
// speedup vs baseline: 2.0016x; 1.3961x over previous
#include <cuda_runtime.h>
#include <cuda_fp16.h>

// ============================================================================
// Sinkhorn, N=8, P=2048, EPS=0.1, 50 iters.
//   a = (mu+1e-8)/(K b),  b = (nu+1e-8)/(K^T a),  b0 = 1,  K = exp(-C/eps)
// K fp16 (67MB, L2-resident). ONE persistent kernel, software grid barrier.
// Each thread owns 8 fixed columns: b in 8 registers (1 load/iter), per-band
// K chunk in 32 registers used for BOTH the row-GEMV (pass1) and the column
// partials (pass2). K traverses L2 once/iter; no smem K staging, no smem b.
// Deterministic (fixed reduction order, no float atomics).
//
// Output (fp32): [ cost(8) | pi(8*2048*2048) | C(8*2048*2048) ],
// pi recomputed from ORIGINAL fp32 C: pi = exp(ln a_i + ln b_j - 10*C_ij).
// ============================================================================

#define N_B   8
#define P     2048
#define NITER 50
#define RB    8                 // rows per band
#define NBANDS (P / RB)         // 256 bands per batch
#define TPB   256
#define MAXBB 64                // max blocks per batch (partials bound)
#define INV_EPS 10.0f

// scratch (static __device__ arrays: the sanctioned scratch mechanism)
static __device__ __half2 K2[(size_t)N_B * P * (P / 2)];     // 67 MB fp16
static __device__ float   partials[(size_t)N_B * MAXBB * P]; // 4 MB
static __device__ float   b_buf[N_B * P];
static __device__ float   a_buf[N_B * P];
static __device__ float   cost_part[N_B * 128];

// software grid barrier (ctr returns to 0 each sync; gen monotonic)
static __device__ unsigned bar_ctr;
static __device__ volatile unsigned bar_gen;

__device__ __forceinline__ void grid_sync(int G) {
    __syncthreads();
    if (threadIdx.x == 0) {
        __threadfence();
        unsigned gen = bar_gen;
        if (atomicAdd(&bar_ctr, 1u) == (unsigned)(G - 1)) {
            bar_ctr = 0;
            __threadfence();
            bar_gen = gen + 1;
        } else {
            while (bar_gen == gen) { }
            __threadfence();
        }
    }
    __syncthreads();
}

// ---------------------------------------------------------------------------
// K = exp(-C/eps), fp32 -> fp16
__global__ __launch_bounds__(256) void k_prep(const float* __restrict__ C) {
    size_t i = (size_t)blockIdx.x * 256 + threadIdx.x;  // float4 idx, 8388608
    float4 c = __ldcs(reinterpret_cast<const float4*>(C) + i);
    K2[2 * i]     = __floats2half2_rn(__expf(-INV_EPS * c.x), __expf(-INV_EPS * c.y));
    K2[2 * i + 1] = __floats2half2_rn(__expf(-INV_EPS * c.z), __expf(-INV_EPS * c.w));
}

// ---------------------------------------------------------------------------
// Persistent iteration kernel. grid = G = 8*Bb blocks, 256 threads.
__global__ __launch_bounds__(TPB) void k_main(const float* __restrict__ mu,
                                              const float* __restrict__ nu,
                                              int G, int Bb) {
    __shared__ float wsum[RB * 8];   // [row][warp] partials
    __shared__ float ash[RB];        // a for current band

    int tid = threadIdx.x;
    int w   = tid >> 5;
    int l   = tid & 31;
    int n   = blockIdx.x / Bb;       // batch
    int r   = blockIdx.x % Bb;       // block index within batch

    // b0 = 1
    for (int e = blockIdx.x * TPB + tid; e < N_B * P; e += G * TPB)
        b_buf[e] = 1.0f;
    grid_sync(G);

    for (int it = 0; it < NITER; it++) {
        // this thread's 8 b-values (columns 8*tid .. 8*tid+7)
        const float4* bb4 = reinterpret_cast<const float4*>(b_buf + n * P) + tid * 2;
        float4 B0 = __ldcg(bb4);
        float4 B1 = __ldcg(bb4 + 1);

        float c0 = 0.f, c1 = 0.f, c2 = 0.f, c3 = 0.f;
        float c4 = 0.f, c5 = 0.f, c6 = 0.f, c7 = 0.f;

        for (int band = r; band < NBANDS; band += Bb) {
            const uint4* Kb = reinterpret_cast<const uint4*>(
                K2 + (size_t)(n * P + band * RB) * (P / 2));
            uint4 kk[RB];

            // pass 1: row dots with register b, warp shfl-reduce
#pragma unroll
            for (int i = 0; i < RB; i++) {
                kk[i] = Kb[(size_t)i * 256 + tid];
                float2 f0 = __half22float2(*reinterpret_cast<__half2*>(&kk[i].x));
                float2 f1 = __half22float2(*reinterpret_cast<__half2*>(&kk[i].y));
                float2 f2 = __half22float2(*reinterpret_cast<__half2*>(&kk[i].z));
                float2 f3 = __half22float2(*reinterpret_cast<__half2*>(&kk[i].w));
                float s = f0.x * B0.x;
                s = fmaf(f0.y, B0.y, s);
                s = fmaf(f1.x, B0.z, s);
                s = fmaf(f1.y, B0.w, s);
                s = fmaf(f2.x, B1.x, s);
                s = fmaf(f2.y, B1.y, s);
                s = fmaf(f3.x, B1.z, s);
                s = fmaf(f3.y, B1.w, s);
#pragma unroll
                for (int o = 16; o; o >>= 1)
                    s += __shfl_down_sync(0xffffffffu, s, o);
                if (l == 0) wsum[i * 8 + w] = s;
            }
            __syncthreads();

            if (tid < RB) {
                float s = 0.f;
#pragma unroll
                for (int j = 0; j < 8; j++) s += wsum[tid * 8 + j];
                int row = band * RB + tid;
                float av = __fdividef(__ldg(mu + n * P + row) + 1e-8f, s);
                ash[tid] = av;
                if (it == NITER - 1) a_buf[n * P + row] = av;
            }
            __syncthreads();

            // pass 2: column partials from the SAME K registers
#pragma unroll
            for (int i = 0; i < RB; i++) {
                float ai = ash[i];
                float2 f0 = __half22float2(*reinterpret_cast<__half2*>(&kk[i].x));
                float2 f1 = __half22float2(*reinterpret_cast<__half2*>(&kk[i].y));
                float2 f2 = __half22float2(*reinterpret_cast<__half2*>(&kk[i].z));
                float2 f3 = __half22float2(*reinterpret_cast<__half2*>(&kk[i].w));
                c0 = fmaf(ai, f0.x, c0);  c1 = fmaf(ai, f0.y, c1);
                c2 = fmaf(ai, f1.x, c2);  c3 = fmaf(ai, f1.y, c3);
                c4 = fmaf(ai, f2.x, c4);  c5 = fmaf(ai, f2.y, c5);
                c6 = fmaf(ai, f3.x, c6);  c7 = fmaf(ai, f3.y, c7);
            }
            // no sync needed: next band's wsum writes race with nothing
            // (wsum reads finished before 2nd sync; ash rewritten only after
            // the next band's own __syncthreads)
        }

        // publish this block's column partials
        float* wp = partials + (size_t)(n * Bb + r) * P + tid * 8;
        *reinterpret_cast<float4*>(wp)     = make_float4(c0, c1, c2, c3);
        *reinterpret_cast<float4*>(wp + 4) = make_float4(c4, c5, c6, c7);

        grid_sync(G);

        // distributed b-reduce: b_j = (nu_j+1e-8) / sum_k partials[k][j]
        for (int e = blockIdx.x * TPB + tid; e < N_B * P; e += G * TPB) {
            int nn = e >> 11, j = e & (P - 1);
            const float* pp = partials + (size_t)nn * Bb * P + j;
            float s = 0.0f;
            for (int k = 0; k < Bb; k++) s += __ldcg(pp + (size_t)k * P);
            b_buf[e] = __fdividef(__ldg(nu + e) + 1e-8f, s);
        }

        grid_sync(G);
    }
}

// ---------------------------------------------------------------------------
// pi = exp(ln a + ln b - 10*C) from ORIGINAL fp32 C; cost partials; C copy
__global__ __launch_bounds__(256) void k_epi(const float* __restrict__ C,
                                             float* __restrict__ pi_out,
                                             float* __restrict__ c_out) {
    int n    = blockIdx.y;
    int row0 = blockIdx.x * 16;
    __shared__ float lbsh[P];
    __shared__ float sred[256];
    for (int j = threadIdx.x; j < P; j += 256)
        lbsh[j] = __logf(b_buf[n * P + j]);
    __syncthreads();
    float local = 0.0f;
    for (int r = 0; r < 16; r++) {
        int row = row0 + r;
        float la = __logf(a_buf[n * P + row]);
        size_t base = ((size_t)n * P + row) * P;
        const float4* Cr = reinterpret_cast<const float4*>(C + base);
        float4* Pr = pi_out ? reinterpret_cast<float4*>(pi_out + base) : nullptr;
        float4* Or = c_out  ? reinterpret_cast<float4*>(c_out  + base) : nullptr;
        for (int q = threadIdx.x; q < P / 4; q += 256) {
            float4 c = __ldcs(Cr + q);
            int j = q * 4;
            float4 pi;
            pi.x = __expf(la + lbsh[j]     - INV_EPS * c.x);
            pi.y = __expf(la + lbsh[j + 1] - INV_EPS * c.y);
            pi.z = __expf(la + lbsh[j + 2] - INV_EPS * c.z);
            pi.w = __expf(la + lbsh[j + 3] - INV_EPS * c.w);
            if (Pr) __stcs(Pr + q, pi);
            if (Or) __stcs(Or + q, c);
            local += pi.x * c.x + pi.y * c.y + pi.z * c.z + pi.w * c.w;
        }
    }
    sred[threadIdx.x] = local;
    __syncthreads();
    for (int o = 128; o; o >>= 1) {
        if (threadIdx.x < o) sred[threadIdx.x] += sred[threadIdx.x + o];
        __syncthreads();
    }
    if (threadIdx.x == 0) cost_part[n * 128 + blockIdx.x] = sred[0];
}

__global__ __launch_bounds__(128) void k_cost(float* __restrict__ out) {
    int n = blockIdx.x;
    __shared__ float s[128];
    s[threadIdx.x] = cost_part[n * 128 + threadIdx.x];
    __syncthreads();
    for (int o = 64; o; o >>= 1) {
        if (threadIdx.x < o) s[threadIdx.x] += s[threadIdx.x + o];
        __syncthreads();
    }
    if (threadIdx.x == 0) out[n] = s[0];
}

// ---------------------------------------------------------------------------
extern "C" void kernel_launch(void* const* d_in, const int* in_sizes, int n_in,
                              void* d_out, int out_size) {
    const float* C  = (const float*)d_in[0];
    const float* mu = (const float*)d_in[1];
    const float* nu = (const float*)d_in[2];
    float* out = (float*)d_out;

    const long long PI_ELEMS = (long long)N_B * P * P;  // 33554432
    float* pi_out = nullptr;
    float* c_out  = nullptr;
    if ((long long)out_size >= 8 + PI_ELEMS)     pi_out = out + 8;
    if ((long long)out_size >= 8 + 2 * PI_ELEMS) c_out  = out + 8 + PI_ELEMS;

    static int G = 0, Bb = 0;
    if (G == 0) {   // host-side, deterministic per process
        int dev = 0, nsm = 148, maxb = 1;
        cudaGetDevice(&dev);
        cudaDeviceGetAttribute(&nsm, cudaDevAttrMultiProcessorCount, dev);
        cudaOccupancyMaxActiveBlocksPerMultiprocessor(&maxb, k_main, TPB, 0);
        if (maxb < 1) maxb = 1;
        long long tot = (long long)nsm * maxb;
        Bb = (int)(tot / N_B);
        if (Bb > MAXBB) Bb = MAXBB;
        if (Bb < 1) Bb = 1;
        G = Bb * N_B;
    }

    k_prep<<<32768, 256>>>(C);
    k_main<<<G, TPB>>>(mu, nu, G, Bb);
    k_epi<<<dim3(128, N_B), 256>>>(C, pi_out, c_out);
    k_cost<<<N_B, 128>>>(out);
}

// round 9
// speedup vs baseline: 2.1434x; 1.0708x over previous
#include <cuda_runtime.h>
#include <cuda_fp16.h>

// ============================================================================
// Sinkhorn, N=8, P=2048, EPS=0.1, 50 iters.
//   a = (mu+1e-8)/(K b),  b = (nu+1e-8)/(K^T a),  b0 = 1,  K = exp(-C/eps)
// K fp16 (67MB, L2-resident). ONE persistent kernel, per-batch software
// barriers (8 independent groups of Bb blocks). Each thread owns 8 fixed
// columns; per 8-row band K is loaded as uint4, converted to float ONCE and
// the same float registers feed both the row-GEMV (pass1) and the column
// partials (pass2). K traverses L2 once/iter. b-reduce parallelized 4
// threads/entry. Deterministic (fixed reduction order, no float atomics).
//
// Output (fp32): [ cost(8) | pi(8*2048*2048) | C(8*2048*2048) ],
// pi recomputed from ORIGINAL fp32 C: pi = exp(ln a_i + ln b_j - 10*C_ij).
// ============================================================================

#define N_B   8
#define P     2048
#define NITER 50
#define RB    8                 // rows per band
#define NBANDS (P / RB)         // 256 bands per batch
#define TPB   256
#define MAXBB 64                // max blocks per batch (partials bound)
#define INV_EPS 10.0f

// scratch (static __device__ arrays: the sanctioned scratch mechanism)
static __device__ __half2 K2[(size_t)N_B * P * (P / 2)];     // 67 MB fp16
static __device__ float   partials[(size_t)N_B * MAXBB * P]; // 4 MB
static __device__ float   b_buf[N_B * P];
static __device__ float   a_buf[N_B * P];
static __device__ float   cost_part[N_B * 128];

// per-batch software barriers (zero-init; ctr returns to 0, gen monotonic)
static __device__ unsigned bbar_ctr[N_B];
static __device__ volatile unsigned bbar_gen[N_B];

__device__ __forceinline__ void batch_sync(int n, int Bb) {
    __syncthreads();
    if (threadIdx.x == 0) {
        __threadfence();
        unsigned gen = bbar_gen[n];
        if (atomicAdd(&bbar_ctr[n], 1u) == (unsigned)(Bb - 1)) {
            bbar_ctr[n] = 0;
            __threadfence();
            bbar_gen[n] = gen + 1;
        } else {
            while (bbar_gen[n] == gen) { }
            __threadfence();
        }
    }
    __syncthreads();
}

// ---------------------------------------------------------------------------
// K = exp(-C/eps), fp32 -> fp16
__global__ __launch_bounds__(256) void k_prep(const float* __restrict__ C) {
    size_t i = (size_t)blockIdx.x * 256 + threadIdx.x;  // float4 idx, 8388608
    float4 c = __ldcs(reinterpret_cast<const float4*>(C) + i);
    K2[2 * i]     = __floats2half2_rn(__expf(-INV_EPS * c.x), __expf(-INV_EPS * c.y));
    K2[2 * i + 1] = __floats2half2_rn(__expf(-INV_EPS * c.z), __expf(-INV_EPS * c.w));
}

// ---------------------------------------------------------------------------
// Persistent iteration kernel. grid = G = 8*Bb blocks, 256 threads.
__global__ __launch_bounds__(TPB) void k_main(const float* __restrict__ mu,
                                              const float* __restrict__ nu,
                                              int Bb) {
    __shared__ float wsum[RB * 8];   // [row][warp] partials
    __shared__ float ash[RB];        // a for current band

    int tid = threadIdx.x;
    int w   = tid >> 5;
    int l   = tid & 31;
    int n   = blockIdx.x / Bb;       // batch
    int r   = blockIdx.x % Bb;       // block index within batch

    // b0 = 1 (each batch inits its own slice)
    for (int e = r * TPB + tid; e < P; e += Bb * TPB)
        b_buf[n * P + e] = 1.0f;
    batch_sync(n, Bb);

    for (int it = 0; it < NITER; it++) {
        // this thread's 8 b-values (columns 8*tid .. 8*tid+7)
        const float4* bb4 = reinterpret_cast<const float4*>(b_buf + n * P) + tid * 2;
        float4 B0 = __ldcg(bb4);
        float4 B1 = __ldcg(bb4 + 1);

        float c0 = 0.f, c1 = 0.f, c2 = 0.f, c3 = 0.f;
        float c4 = 0.f, c5 = 0.f, c6 = 0.f, c7 = 0.f;

        for (int band = r; band < NBANDS; band += Bb) {
            const uint4* Kb = reinterpret_cast<const uint4*>(
                K2 + (size_t)(n * P + band * RB) * (P / 2));

            // K floats, converted ONCE, reused by both passes
            float kf[RB][8];

            // pass 1: row dots with register b, warp shfl-reduce
#pragma unroll
            for (int i = 0; i < RB; i++) {
                uint4 kk = Kb[(size_t)i * 256 + tid];
                float2 f0 = __half22float2(*reinterpret_cast<__half2*>(&kk.x));
                float2 f1 = __half22float2(*reinterpret_cast<__half2*>(&kk.y));
                float2 f2 = __half22float2(*reinterpret_cast<__half2*>(&kk.z));
                float2 f3 = __half22float2(*reinterpret_cast<__half2*>(&kk.w));
                kf[i][0] = f0.x; kf[i][1] = f0.y;
                kf[i][2] = f1.x; kf[i][3] = f1.y;
                kf[i][4] = f2.x; kf[i][5] = f2.y;
                kf[i][6] = f3.x; kf[i][7] = f3.y;
                float s = f0.x * B0.x;
                s = fmaf(f0.y, B0.y, s);
                s = fmaf(f1.x, B0.z, s);
                s = fmaf(f1.y, B0.w, s);
                s = fmaf(f2.x, B1.x, s);
                s = fmaf(f2.y, B1.y, s);
                s = fmaf(f3.x, B1.z, s);
                s = fmaf(f3.y, B1.w, s);
#pragma unroll
                for (int o = 16; o; o >>= 1)
                    s += __shfl_down_sync(0xffffffffu, s, o);
                if (l == 0) wsum[i * 8 + w] = s;
            }
            __syncthreads();

            if (tid < RB) {
                float s = 0.f;
#pragma unroll
                for (int j = 0; j < 8; j++) s += wsum[tid * 8 + j];
                int row = band * RB + tid;
                float av = __fdividef(__ldg(mu + n * P + row) + 1e-8f, s);
                ash[tid] = av;
                if (it == NITER - 1) a_buf[n * P + row] = av;
            }
            __syncthreads();

            // pass 2: column partials from the SAME float registers
#pragma unroll
            for (int i = 0; i < RB; i++) {
                float ai = ash[i];
                c0 = fmaf(ai, kf[i][0], c0);  c1 = fmaf(ai, kf[i][1], c1);
                c2 = fmaf(ai, kf[i][2], c2);  c3 = fmaf(ai, kf[i][3], c3);
                c4 = fmaf(ai, kf[i][4], c4);  c5 = fmaf(ai, kf[i][5], c5);
                c6 = fmaf(ai, kf[i][6], c6);  c7 = fmaf(ai, kf[i][7], c7);
            }
            // no extra sync needed: ash is rewritten only after the next
            // band's sync1, by which time all pass-2 reads are done.
        }

        // publish this block's column partials
        float* wp = partials + (size_t)(n * Bb + r) * P + tid * 8;
        *reinterpret_cast<float4*>(wp)     = make_float4(c0, c1, c2, c3);
        *reinterpret_cast<float4*>(wp + 4) = make_float4(c4, c5, c6, c7);

        batch_sync(n, Bb);

        // distributed b-reduce (batch-local): 4 threads per column entry,
        // 4 independent accumulators for MLP, shfl-combine in 4-lane groups.
        {
            int t = r * TPB + tid;              // 0 .. Bb*256-1
            int e = t >> 2;                     // column entry
            int q = t & 3;                      // lane within 4-group
            float s0 = 0.f, s1 = 0.f, s2 = 0.f, s3 = 0.f;
            if (e < P) {
                const float* pp = partials + (size_t)n * Bb * P + e;
                int k = q;
                for (; k + 12 < Bb; k += 16) {
                    s0 += __ldcg(pp + (size_t)k * P);
                    s1 += __ldcg(pp + (size_t)(k + 4) * P);
                    s2 += __ldcg(pp + (size_t)(k + 8) * P);
                    s3 += __ldcg(pp + (size_t)(k + 12) * P);
                }
                for (; k < Bb; k += 4) s0 += __ldcg(pp + (size_t)k * P);
            }
            float s = (s0 + s1) + (s2 + s3);
            s += __shfl_down_sync(0xffffffffu, s, 1, 4);
            s += __shfl_down_sync(0xffffffffu, s, 2, 4);
            if (e < P && q == 0)
                b_buf[n * P + e] = __fdividef(__ldg(nu + n * P + e) + 1e-8f, s);
        }

        batch_sync(n, Bb);
    }
}

// ---------------------------------------------------------------------------
// pi = exp(ln a + ln b - 10*C) from ORIGINAL fp32 C; cost partials; C copy
__global__ __launch_bounds__(256) void k_epi(const float* __restrict__ C,
                                             float* __restrict__ pi_out,
                                             float* __restrict__ c_out) {
    int n    = blockIdx.y;
    int row0 = blockIdx.x * 16;
    __shared__ float lbsh[P];
    __shared__ float sred[256];
    for (int j = threadIdx.x; j < P; j += 256)
        lbsh[j] = __logf(b_buf[n * P + j]);
    __syncthreads();
    float local = 0.0f;
    for (int r = 0; r < 16; r++) {
        int row = row0 + r;
        float la = __logf(a_buf[n * P + row]);
        size_t base = ((size_t)n * P + row) * P;
        const float4* Cr = reinterpret_cast<const float4*>(C + base);
        float4* Pr = pi_out ? reinterpret_cast<float4*>(pi_out + base) : nullptr;
        float4* Or = c_out  ? reinterpret_cast<float4*>(c_out  + base) : nullptr;
        for (int q = threadIdx.x; q < P / 4; q += 256) {
            float4 c = __ldcs(Cr + q);
            int j = q * 4;
            float4 pi;
            pi.x = __expf(la + lbsh[j]     - INV_EPS * c.x);
            pi.y = __expf(la + lbsh[j + 1] - INV_EPS * c.y);
            pi.z = __expf(la + lbsh[j + 2] - INV_EPS * c.z);
            pi.w = __expf(la + lbsh[j + 3] - INV_EPS * c.w);
            if (Pr) __stcs(Pr + q, pi);
            if (Or) __stcs(Or + q, c);
            local += pi.x * c.x + pi.y * c.y + pi.z * c.z + pi.w * c.w;
        }
    }
    sred[threadIdx.x] = local;
    __syncthreads();
    for (int o = 128; o; o >>= 1) {
        if (threadIdx.x < o) sred[threadIdx.x] += sred[threadIdx.x + o];
        __syncthreads();
    }
    if (threadIdx.x == 0) cost_part[n * 128 + blockIdx.x] = sred[0];
}

__global__ __launch_bounds__(128) void k_cost(float* __restrict__ out) {
    int n = blockIdx.x;
    __shared__ float s[128];
    s[threadIdx.x] = cost_part[n * 128 + threadIdx.x];
    __syncthreads();
    for (int o = 64; o; o >>= 1) {
        if (threadIdx.x < o) s[threadIdx.x] += s[threadIdx.x + o];
        __syncthreads();
    }
    if (threadIdx.x == 0) out[n] = s[0];
}

// ---------------------------------------------------------------------------
extern "C" void kernel_launch(void* const* d_in, const int* in_sizes, int n_in,
                              void* d_out, int out_size) {
    const float* C  = (const float*)d_in[0];
    const float* mu = (const float*)d_in[1];
    const float* nu = (const float*)d_in[2];
    float* out = (float*)d_out;

    const long long PI_ELEMS = (long long)N_B * P * P;  // 33554432
    float* pi_out = nullptr;
    float* c_out  = nullptr;
    if ((long long)out_size >= 8 + PI_ELEMS)     pi_out = out + 8;
    if ((long long)out_size >= 8 + 2 * PI_ELEMS) c_out  = out + 8 + PI_ELEMS;

    static int G = 0, Bb = 0;
    if (G == 0) {   // host-side, deterministic per process
        int dev = 0, nsm = 148, maxb = 1;
        cudaGetDevice(&dev);
        cudaDeviceGetAttribute(&nsm, cudaDevAttrMultiProcessorCount, dev);
        cudaOccupancyMaxActiveBlocksPerMultiprocessor(&maxb, k_main, TPB, 0);
        if (maxb < 1) maxb = 1;
        long long tot = (long long)nsm * maxb;
        Bb = (int)(tot / N_B);
        if (Bb > MAXBB) Bb = MAXBB;
        if (Bb < 32) Bb = 32;   // b-reduce needs Bb*256 >= 4*P threads
        G = Bb * N_B;
    }

    k_prep<<<32768, 256>>>(C);
    k_main<<<G, TPB>>>(mu, nu, Bb);
    k_epi<<<dim3(128, N_B), 256>>>(C, pi_out, c_out);
    k_cost<<<N_B, 128>>>(out);
}